// round 15
// baseline (speedup 1.0000x reference)
#include <cuda_runtime.h>
#include <cuda_fp16.h>
#include <cstdint>

#define NA 65536
#define D  256
#define TT 4
#define TM 64
#define NTILES (NA / TM)   // 1024
#define NTH 256
#define SAW 132            // A row stride in u32 (264 halves)

// ---- shared memory byte offsets ----
#define OFF_A_B   0                      // A tile fp16: 64 x 132 u32 = 33792 B
#define OFF_X_B   33792                  // x residual fp16: 64 x 128 u32 = 32768
#define OFF_RED_B 66560                  // 1024 floats = 4096 B
#define OFF_ST_B  70656                  // 128 floats mu/inv = 512
#define SMEM_BYTES 71168

// ---------------- device scratch ----------------
__device__ int nn_off[TT + 1];
__device__ int nn_cur[TT];
__device__ int nn_perm[NA];
// fp16 frag weights: [mat(4)][species(4)][chunk(16)][g(32)][lane(32)][2xu32] = 2MB
__device__ __align__(16) uint32_t nn_wfragh[4 * TT * 16 * 2048];

// ---------------- combined init+hist+prefix ----------------
__global__ void nn_combo(const int* __restrict__ sp) {
    __shared__ int c[TT];
    int tid = threadIdx.x;
    if (tid < TT) { c[tid] = 0; nn_cur[tid] = 0; }
    __syncthreads();
    int l0 = 0, l1 = 0, l2 = 0, l3 = 0;
    for (int i = tid; i < NA / 4; i += 1024) {
        int4 v = __ldg((const int4*)sp + i);
        l0 += (v.x == 0) + (v.y == 0) + (v.z == 0) + (v.w == 0);
        l1 += (v.x == 1) + (v.y == 1) + (v.z == 1) + (v.w == 1);
        l2 += (v.x == 2) + (v.y == 2) + (v.z == 2) + (v.w == 2);
        l3 += (v.x == 3) + (v.y == 3) + (v.z == 3) + (v.w == 3);
    }
    if (l0) atomicAdd(&c[0], l0);
    if (l1) atomicAdd(&c[1], l1);
    if (l2) atomicAdd(&c[2], l2);
    if (l3) atomicAdd(&c[3], l3);
    __syncthreads();
    if (tid == 0) {
        int a = 0;
        for (int s = 0; s < TT; s++) { nn_off[s] = a; a += c[s]; }
        nn_off[TT] = a;
    }
}

__global__ void nn_scatter(const int* __restrict__ sp) {
    __shared__ int lc[TT];
    __shared__ int lb[TT];
    int tid = threadIdx.x;
    if (tid < TT) lc[tid] = 0;
    __syncthreads();
    int i = blockIdx.x * blockDim.x + tid;
    int s = 0, pos = 0;
    if (i < NA) { s = sp[i]; pos = atomicAdd(&lc[s], 1); }
    __syncthreads();
    if (tid < TT) {
        int n = lc[tid];
        lb[tid] = (n > 0) ? atomicAdd(&nn_cur[tid], n) : 0;
    }
    __syncthreads();
    if (i < NA) nn_perm[nn_off[s] + lb[s] + pos] = i;
}

// ---------------- helpers ----------------
__device__ __forceinline__ uint32_t h2u(float a, float b) {
    __half2 h = __floats2half2_rn(a, b);
    return *(uint32_t*)&h;
}
__device__ __forceinline__ float2 u2f(uint32_t u) {
    __half2 h = *(__half2*)&u;
    return __half22float2(h);
}
__device__ __forceinline__ uint32_t s2u(const void* p) {
    uint32_t a;
    asm("{ .reg .u64 t; cvta.to.shared.u64 t, %1; cvt.u32.u64 %0, t; }" : "=r"(a) : "l"(p));
    return a;
}

__device__ __forceinline__ void mma16(float* d, const uint32_t* a, const uint32_t* b) {
    asm volatile("mma.sync.aligned.m16n8k16.row.col.f32.f16.f16.f32 "
                 "{%0,%1,%2,%3}, {%4,%5,%6,%7}, {%8,%9}, {%0,%1,%2,%3};"
                 : "+f"(d[0]), "+f"(d[1]), "+f"(d[2]), "+f"(d[3])
                 : "r"(a[0]), "r"(a[1]), "r"(a[2]), "r"(a[3]), "r"(b[0]), "r"(b[1]));
}
__device__ __forceinline__ void ldm4(uint32_t* a, uint32_t addr) {
    asm volatile("ldmatrix.sync.aligned.m8n8.x4.shared.b16 {%0,%1,%2,%3}, [%4];"
                 : "=r"(a[0]), "=r"(a[1]), "=r"(a[2]), "=r"(a[3]) : "r"(addr));
}
__device__ __forceinline__ float silu_s(float z) {
    return z * (1.f / (1.f + __expf(-z)));
}

// ---------------- weight prepass: fp16 fragment packing ----------------
__global__ void nn_prep(const float* __restrict__ W0, const float* __restrict__ Wa,
                        const float* __restrict__ Wl, const float* __restrict__ Wf) {
    int p = blockIdx.x * 256 + threadIdx.x;
    int l = p & 31;
    int g = (p >> 5) & 31;
    int c = (p >> 10) & 15;
    int s = (p >> 14) & 3;
    int m = p >> 16;
    const float* W = (m == 0 ? W0 : m == 1 ? Wa : m == 2 ? Wl : Wf) + s * D * D;
    int n  = g * 8 + (l >> 2);
    int k0 = c * 16 + (l & 3) * 2;
    const float* wr = W + n * D;
    nn_wfragh[2 * p]     = h2u(__ldg(wr + k0),     __ldg(wr + k0 + 1));
    nn_wfragh[2 * p + 1] = h2u(__ldg(wr + k0 + 8), __ldg(wr + k0 + 9));
}

// ---------------- 64x256x256 GEMM: B global->regs, A ldmatrix double-buffered ----------------
// wp: this lane's B fragment pointer at chunk 0, group 4*warp (uint2 units).
__device__ __forceinline__ void gemm64(uint32_t aBase, const uint2* __restrict__ wp,
                                       float acc[4][4][4]) {
    uint2 bv[2][4];
#pragma unroll
    for (int nt = 0; nt < 4; nt++) bv[0][nt] = __ldg(wp + nt * 32);
#pragma unroll
    for (int nt = 0; nt < 4; nt++) bv[1][nt] = __ldg(wp + 1024 + nt * 32);
    uint32_t a[2][4][4];
#pragma unroll
    for (int mt = 0; mt < 4; mt++)
        ldm4(a[0][mt], aBase + (uint32_t)(mt * 16 * SAW * 4));
#pragma unroll
    for (int c = 0; c < 16; c++) {
        const int cur = c & 1;
        // prefetch next chunk's A fragments while this chunk's MMAs run
        if (c + 1 < 16) {
#pragma unroll
            for (int mt = 0; mt < 4; mt++)
                ldm4(a[1 - cur][mt], aBase + (uint32_t)(mt * 16 * SAW * 4 + (c + 1) * 32));
        }
#pragma unroll
        for (int mt = 0; mt < 4; mt++)
#pragma unroll
            for (int nt = 0; nt < 4; nt++)
                mma16(acc[mt][nt], a[cur][mt], (const uint32_t*)&bv[cur][nt]);
        if (c + 2 < 16) {
#pragma unroll
            for (int nt = 0; nt < 4; nt++)
                bv[cur][nt] = __ldg(wp + (c + 2) * 1024 + nt * 32);
        }
    }
}

#define ZACC(acc) \
    _Pragma("unroll") for (int mt = 0; mt < 4; mt++) \
    _Pragma("unroll") for (int nt = 0; nt < 4; nt++) \
    _Pragma("unroll") for (int q = 0; q < 4; q++) (acc)[mt][nt][q] = 0.f;

// ---------------- fused expert MLP ----------------
__global__ void __launch_bounds__(NTH, 2)
nn_fused(const float* __restrict__ density,
         const float* __restrict__ b0, const float* __restrict__ ba,
         const float* __restrict__ alpha_a, const float* __restrict__ gamma,
         const float* __restrict__ beta_ln, const float* __restrict__ bl,
         const float* __restrict__ bf, const float* __restrict__ alpha_f,
         const float* __restrict__ Wo, const float* __restrict__ bo,
         float* __restrict__ out) {
    extern __shared__ char smraw[];
    uint32_t* smA   = (uint32_t*)(smraw + OFF_A_B);
    uint32_t* smX   = (uint32_t*)(smraw + OFF_X_B);
    float*    red   = (float*)(smraw + OFF_RED_B);
    float*    stats = (float*)(smraw + OFF_ST_B);
    const uint32_t sA_u32 = s2u(smA);

    const int tid = threadIdx.x;
    const int warp = tid >> 5;
    const int lane = tid & 31;
    const int qr = lane >> 2, qc = lane & 3;
    const int row0 = blockIdx.x * TM;
    const uint32_t aBase = sA_u32 + (uint32_t)((lane & 15) * SAW * 4 + (lane >> 4) * 16);
    const int wlofs = (4 * warp) * 32 + lane;   // uint2 offset of this lane's frags

    for (int s = 0; s < TT; s++) {
        const int lo = max(row0, nn_off[s]);
        const int hi = min(row0 + TM, nn_off[s + 1]);
        if (lo >= hi) continue;
        __syncthreads();   // prior species fully done with smA/smX

        const uint2* wp0 = (const uint2*)(nn_wfragh + (size_t)(0 * 4 + s) * 32768) + wlofs;
        const uint2* wp1 = (const uint2*)(nn_wfragh + (size_t)(1 * 4 + s) * 32768) + wlofs;
        const uint2* wp2 = (const uint2*)(nn_wfragh + (size_t)(2 * 4 + s) * 32768) + wlofs;
        const uint2* wp3 = (const uint2*)(nn_wfragh + (size_t)(3 * 4 + s) * 32768) + wlofs;
        const float* b0s = b0 + s * D;
        const float* bas = ba + s * D;
        const float* aas = alpha_a + s * D;
        const float* gs  = gamma + s * D;
        const float* bts = beta_ln + s * D;
        const float* bls = bl + s * D;
        const float* bfs = bf + s * D;
        const float* afs = alpha_f + s * D;
        const float* wos = Wo + s * D;

        // gather density rows (fp16 into A)
#pragma unroll
        for (int it = 0; it < 16; it++) {
            int q = it * 256 + tid;
            int r = q >> 6, j = q & 63;
            uint2 t = make_uint2(0u, 0u);
            int gr = row0 + r;
            if (gr >= lo && gr < hi) {
                float4 v = __ldg((const float4*)(density + (size_t)nn_perm[gr] * D + j * 4));
                t = make_uint2(h2u(v.x, v.y), h2u(v.z, v.w));
            }
            *(uint2*)(smA + r * SAW + j * 2) = t;
        }
        __syncthreads();   // A ready for gemm

        float acc[4][4][4];

        // ===== layer 0: x = A @ W0^T + b0 (fp16(x) -> A and smX) =====
        ZACC(acc);
        gemm64(aBase, wp0, acc);
        __syncthreads();   // all warps done reading A
#pragma unroll
        for (int mt = 0; mt < 4; mt++)
#pragma unroll
            for (int nt = 0; nt < 4; nt++) {
                const int c0 = warp * 32 + nt * 8 + 2 * qc;
                float2 b2 = __ldg((const float2*)(b0s + c0));
                float z0 = acc[mt][nt][0] + b2.x, z1 = acc[mt][nt][1] + b2.y;
                float z2 = acc[mt][nt][2] + b2.x, z3 = acc[mt][nt][3] + b2.y;
                const int rr = mt * 16 + qr, cw = warp * 16 + nt * 4 + qc;
                uint32_t u0 = h2u(z0, z1), u1 = h2u(z2, z3);
                smA[rr * SAW + cw]       = u0;
                smA[(rr + 8) * SAW + cw] = u1;
                smX[rr * 128 + cw]       = u0;
                smX[(rr + 8) * 128 + cw] = u1;
            }
        __syncthreads();   // A ready

        // ===== hidden: h = LN(alpha_a * silu(x @ Wa^T + ba)) -> A =====
        ZACC(acc);
        gemm64(aBase, wp1, acc);
        __syncthreads();
        {
            float rs[8], rq[8];
#pragma unroll
            for (int i = 0; i < 8; i++) { rs[i] = 0.f; rq[i] = 0.f; }
#pragma unroll
            for (int mt = 0; mt < 4; mt++)
#pragma unroll
                for (int nt = 0; nt < 4; nt++) {
                    const int c0 = warp * 32 + nt * 8 + 2 * qc;
                    float2 b2 = __ldg((const float2*)(bas + c0));
                    float2 a2 = __ldg((const float2*)(aas + c0));
                    float h0 = a2.x * silu_s(acc[mt][nt][0] + b2.x);
                    float h1 = a2.y * silu_s(acc[mt][nt][1] + b2.y);
                    float h2 = a2.x * silu_s(acc[mt][nt][2] + b2.x);
                    float h3 = a2.y * silu_s(acc[mt][nt][3] + b2.y);
                    acc[mt][nt][0] = h0; acc[mt][nt][1] = h1;
                    acc[mt][nt][2] = h2; acc[mt][nt][3] = h3;
                    rs[mt * 2] += h0 + h1;       rq[mt * 2] += h0 * h0 + h1 * h1;
                    rs[mt * 2 + 1] += h2 + h3;   rq[mt * 2 + 1] += h2 * h2 + h3 * h3;
                }
#pragma unroll
            for (int i = 0; i < 8; i++) {
                rs[i] += __shfl_xor_sync(0xffffffffu, rs[i], 1);
                rs[i] += __shfl_xor_sync(0xffffffffu, rs[i], 2);
                rq[i] += __shfl_xor_sync(0xffffffffu, rq[i], 1);
                rq[i] += __shfl_xor_sync(0xffffffffu, rq[i], 2);
            }
            if (qc == 0) {
#pragma unroll
                for (int mt = 0; mt < 4; mt++) {
                    int r0 = mt * 16 + qr;
                    red[r0 * 8 + warp] = rs[mt * 2];
                    red[512 + r0 * 8 + warp] = rq[mt * 2];
                    red[(r0 + 8) * 8 + warp] = rs[mt * 2 + 1];
                    red[512 + (r0 + 8) * 8 + warp] = rq[mt * 2 + 1];
                }
            }
            __syncthreads();
            if (tid < 64) {
                float su = 0.f, sq = 0.f;
#pragma unroll
                for (int w = 0; w < 8; w++) { su += red[tid * 8 + w]; sq += red[512 + tid * 8 + w]; }
                float mu = su * (1.0f / D);
                stats[2 * tid] = mu;
                stats[2 * tid + 1] = rsqrtf(sq * (1.0f / D) - mu * mu + 1e-5f);
            }
            __syncthreads();
#pragma unroll
            for (int mt = 0; mt < 4; mt++) {
                const int rr = mt * 16 + qr;
                float2 st0 = *(const float2*)(stats + 2 * rr);
                float2 st1 = *(const float2*)(stats + 2 * (rr + 8));
#pragma unroll
                for (int nt = 0; nt < 4; nt++) {
                    const int c0 = warp * 32 + nt * 8 + 2 * qc;
                    float2 g2 = __ldg((const float2*)(gs + c0));
                    float2 bt2 = __ldg((const float2*)(bts + c0));
                    float n0 = g2.x * (acc[mt][nt][0] - st0.x) * st0.y + bt2.x;
                    float n1 = g2.y * (acc[mt][nt][1] - st0.x) * st0.y + bt2.y;
                    float n2 = g2.x * (acc[mt][nt][2] - st1.x) * st1.y + bt2.x;
                    float n3 = g2.y * (acc[mt][nt][3] - st1.x) * st1.y + bt2.y;
                    const int cw = warp * 16 + nt * 4 + qc;
                    smA[rr * SAW + cw]       = h2u(n0, n1);
                    smA[(rr + 8) * SAW + cw] = h2u(n2, n3);
                }
            }
        }
        __syncthreads();   // A ready

        // ===== residual: y = x + h @ Wl^T + bl =====
        ZACC(acc);
        gemm64(aBase, wp2, acc);
        __syncthreads();
#pragma unroll
        for (int mt = 0; mt < 4; mt++)
#pragma unroll
            for (int nt = 0; nt < 4; nt++) {
                const int c0 = warp * 32 + nt * 8 + 2 * qc;
                float2 b2 = __ldg((const float2*)(bls + c0));
                const int rr = mt * 16 + qr, cw = warp * 16 + nt * 4 + qc;
                float2 x0 = u2f(smX[rr * 128 + cw]);
                float2 x1 = u2f(smX[(rr + 8) * 128 + cw]);
                float y0 = x0.x + acc[mt][nt][0] + b2.x;
                float y1 = x0.y + acc[mt][nt][1] + b2.y;
                float y2 = x1.x + acc[mt][nt][2] + b2.x;
                float y3 = x1.y + acc[mt][nt][3] + b2.y;
                smA[rr * SAW + cw]       = h2u(y0, y1);
                smA[(rr + 8) * SAW + cw] = h2u(y2, y3);
            }
        __syncthreads();   // A ready

        // ===== tail: f = alpha_f * silu(y @ Wf^T + bf); out = f . Wo + bo =====
        ZACC(acc);
        gemm64(aBase, wp3, acc);
        {
            float rs[8];
#pragma unroll
            for (int i = 0; i < 8; i++) rs[i] = 0.f;
#pragma unroll
            for (int mt = 0; mt < 4; mt++)
#pragma unroll
                for (int nt = 0; nt < 4; nt++) {
                    const int c0 = warp * 32 + nt * 8 + 2 * qc;
                    float2 b2 = __ldg((const float2*)(bfs + c0));
                    float2 a2 = __ldg((const float2*)(afs + c0));
                    float2 w2 = __ldg((const float2*)(wos + c0));
                    rs[mt * 2]     += a2.x * silu_s(acc[mt][nt][0] + b2.x) * w2.x
                                    + a2.y * silu_s(acc[mt][nt][1] + b2.y) * w2.y;
                    rs[mt * 2 + 1] += a2.x * silu_s(acc[mt][nt][2] + b2.x) * w2.x
                                    + a2.y * silu_s(acc[mt][nt][3] + b2.y) * w2.y;
                }
#pragma unroll
            for (int i = 0; i < 8; i++) {
                rs[i] += __shfl_xor_sync(0xffffffffu, rs[i], 1);
                rs[i] += __shfl_xor_sync(0xffffffffu, rs[i], 2);
            }
            __syncthreads();   // red free from LN use
            if (qc == 0) {
#pragma unroll
                for (int mt = 0; mt < 4; mt++) {
                    int r0 = mt * 16 + qr;
                    red[r0 * 8 + warp] = rs[mt * 2];
                    red[(r0 + 8) * 8 + warp] = rs[mt * 2 + 1];
                }
            }
            __syncthreads();
            if (tid < 64) {
                int gr = row0 + tid;
                if (gr >= lo && gr < hi) {
                    float t = 0.f;
#pragma unroll
                    for (int w = 0; w < 8; w++) t += red[tid * 8 + w];
                    out[nn_perm[gr]] = t + __ldg(bo + s);
                }
            }
        }
    }
}

// ---------------- launch ----------------
extern "C" void kernel_launch(void* const* d_in, const int* in_sizes, int n_in,
                              void* d_out, int out_size) {
    const float* density = (const float*)d_in[0];
    const int*   species = (const int*)d_in[1];
    const float* W0      = (const float*)d_in[2];
    const float* b0      = (const float*)d_in[3];
    const float* Wa      = (const float*)d_in[4];
    const float* ba      = (const float*)d_in[5];
    const float* alpha_a = (const float*)d_in[6];
    const float* gamma   = (const float*)d_in[7];
    const float* beta_ln = (const float*)d_in[8];
    const float* Wl      = (const float*)d_in[9];
    const float* bl      = (const float*)d_in[10];
    const float* Wf      = (const float*)d_in[11];
    const float* bf      = (const float*)d_in[12];
    const float* alpha_f = (const float*)d_in[13];
    const float* Wo      = (const float*)d_in[14];
    const float* bo      = (const float*)d_in[15];
    float* out = (float*)d_out;

    cudaFuncSetAttribute(nn_fused, cudaFuncAttributeMaxDynamicSharedMemorySize, SMEM_BYTES);

    nn_combo<<<1, 1024>>>(species);
    nn_scatter<<<NA / 256, 256>>>(species);
    nn_prep<<<1024, 256>>>(W0, Wa, Wl, Wf);
    nn_fused<<<NTILES, NTH, SMEM_BYTES>>>(density, b0, ba, alpha_a, gamma, beta_ln,
                                          bl, bf, alpha_f, Wo, bo, out);
}

// round 16
// speedup vs baseline: 1.1055x; 1.1055x over previous
#include <cuda_runtime.h>
#include <cuda_fp16.h>
#include <cstdint>

#define NA 65536
#define D  256
#define TT 4
#define TM 32
#define NTILES (NA / TM)   // 2048
#define NTH 256
#define SAW 132            // A row stride in u32 (264 halves)

// ---- shared memory byte offsets ----
#define OFF_A_B   0                      // A tile fp16: 32 x 132 u32 = 16896 B
#define OFF_X_B   16896                  // x residual fp16: 32 x 128 u32 = 16384 B
#define OFF_RED_B 33280                  // 512 floats = 2048 B
#define OFF_ST_B  35328                  // 64 floats mu/inv = 256 B
#define SMEM_BYTES 35584

// ---------------- device scratch ----------------
__device__ int nn_off[TT + 1];
__device__ int nn_cur[TT];
__device__ int nn_perm[NA];
// fp16 frag weights: [mat(4)][species(4)][chunk(16)][g(32)][lane(32)][2xu32] = 2MB
__device__ __align__(16) uint32_t nn_wfragh[4 * TT * 16 * 2048];

// ---------------- combined init+hist+prefix ----------------
__global__ void nn_combo(const int* __restrict__ sp) {
    __shared__ int c[TT];
    int tid = threadIdx.x;
    if (tid < TT) { c[tid] = 0; nn_cur[tid] = 0; }
    __syncthreads();
    int l0 = 0, l1 = 0, l2 = 0, l3 = 0;
    for (int i = tid; i < NA / 4; i += 1024) {
        int4 v = __ldg((const int4*)sp + i);
        l0 += (v.x == 0) + (v.y == 0) + (v.z == 0) + (v.w == 0);
        l1 += (v.x == 1) + (v.y == 1) + (v.z == 1) + (v.w == 1);
        l2 += (v.x == 2) + (v.y == 2) + (v.z == 2) + (v.w == 2);
        l3 += (v.x == 3) + (v.y == 3) + (v.z == 3) + (v.w == 3);
    }
    if (l0) atomicAdd(&c[0], l0);
    if (l1) atomicAdd(&c[1], l1);
    if (l2) atomicAdd(&c[2], l2);
    if (l3) atomicAdd(&c[3], l3);
    __syncthreads();
    if (tid == 0) {
        int a = 0;
        for (int s = 0; s < TT; s++) { nn_off[s] = a; a += c[s]; }
        nn_off[TT] = a;
    }
}

__global__ void nn_scatter(const int* __restrict__ sp) {
    __shared__ int lc[TT];
    __shared__ int lb[TT];
    int tid = threadIdx.x;
    if (tid < TT) lc[tid] = 0;
    __syncthreads();
    int i = blockIdx.x * blockDim.x + tid;
    int s = 0, pos = 0;
    if (i < NA) { s = sp[i]; pos = atomicAdd(&lc[s], 1); }
    __syncthreads();
    if (tid < TT) {
        int n = lc[tid];
        lb[tid] = (n > 0) ? atomicAdd(&nn_cur[tid], n) : 0;
    }
    __syncthreads();
    if (i < NA) nn_perm[nn_off[s] + lb[s] + pos] = i;
}

// ---------------- helpers ----------------
__device__ __forceinline__ uint32_t h2u(float a, float b) {
    __half2 h = __floats2half2_rn(a, b);
    return *(uint32_t*)&h;
}
__device__ __forceinline__ float2 u2f(uint32_t u) {
    __half2 h = *(__half2*)&u;
    return __half22float2(h);
}
__device__ __forceinline__ uint32_t s2u(const void* p) {
    uint32_t a;
    asm("{ .reg .u64 t; cvta.to.shared.u64 t, %1; cvt.u32.u64 %0, t; }" : "=r"(a) : "l"(p));
    return a;
}

__device__ __forceinline__ void mma16(float* d, const uint32_t* a, const uint32_t* b) {
    asm volatile("mma.sync.aligned.m16n8k16.row.col.f32.f16.f16.f32 "
                 "{%0,%1,%2,%3}, {%4,%5,%6,%7}, {%8,%9}, {%0,%1,%2,%3};"
                 : "+f"(d[0]), "+f"(d[1]), "+f"(d[2]), "+f"(d[3])
                 : "r"(a[0]), "r"(a[1]), "r"(a[2]), "r"(a[3]), "r"(b[0]), "r"(b[1]));
}
__device__ __forceinline__ void ldm4(uint32_t* a, uint32_t addr) {
    asm volatile("ldmatrix.sync.aligned.m8n8.x4.shared.b16 {%0,%1,%2,%3}, [%4];"
                 : "=r"(a[0]), "=r"(a[1]), "=r"(a[2]), "=r"(a[3]) : "r"(addr));
}
__device__ __forceinline__ float silu_s(float z) {
    return z * (1.f / (1.f + __expf(-z)));
}

// ---------------- weight prepass: fp16 fragment packing ----------------
__global__ void nn_prep(const float* __restrict__ W0, const float* __restrict__ Wa,
                        const float* __restrict__ Wl, const float* __restrict__ Wf) {
    int p = blockIdx.x * 256 + threadIdx.x;
    int l = p & 31;
    int g = (p >> 5) & 31;
    int c = (p >> 10) & 15;
    int s = (p >> 14) & 3;
    int m = p >> 16;
    const float* W = (m == 0 ? W0 : m == 1 ? Wa : m == 2 ? Wl : Wf) + s * D * D;
    int n  = g * 8 + (l >> 2);
    int k0 = c * 16 + (l & 3) * 2;
    const float* wr = W + n * D;
    nn_wfragh[2 * p]     = h2u(__ldg(wr + k0),     __ldg(wr + k0 + 1));
    nn_wfragh[2 * p + 1] = h2u(__ldg(wr + k0 + 8), __ldg(wr + k0 + 9));
}

// ---------------- 32x256x256 GEMM: B global->regs double-buffered, A ldmatrix ----------------
// wp: this lane's B fragment pointer at chunk 0, group 4*warp (uint2 units).
__device__ __forceinline__ void gemm32(uint32_t aBase, const uint2* __restrict__ wp,
                                       float acc[2][4][4]) {
    uint2 bv[2][4];
#pragma unroll
    for (int nt = 0; nt < 4; nt++) bv[0][nt] = __ldg(wp + nt * 32);
#pragma unroll
    for (int nt = 0; nt < 4; nt++) bv[1][nt] = __ldg(wp + 1024 + nt * 32);
#pragma unroll
    for (int c = 0; c < 16; c++) {
        const int cur = c & 1;
        uint32_t a[2][4];
#pragma unroll
        for (int mt = 0; mt < 2; mt++)
            ldm4(a[mt], aBase + (uint32_t)(mt * 16 * SAW * 4 + c * 32));
#pragma unroll
        for (int mt = 0; mt < 2; mt++)
#pragma unroll
            for (int nt = 0; nt < 4; nt++)
                mma16(acc[mt][nt], a[mt], (const uint32_t*)&bv[cur][nt]);
        if (c + 2 < 16) {
#pragma unroll
            for (int nt = 0; nt < 4; nt++)
                bv[cur][nt] = __ldg(wp + (c + 2) * 1024 + nt * 32);
        }
    }
}

#define ZACC(acc) \
    _Pragma("unroll") for (int mt = 0; mt < 2; mt++) \
    _Pragma("unroll") for (int nt = 0; nt < 4; nt++) \
    _Pragma("unroll") for (int q = 0; q < 4; q++) (acc)[mt][nt][q] = 0.f;

// ---------------- fused expert MLP ----------------
__global__ void __launch_bounds__(NTH, 3)
nn_fused(const float* __restrict__ density,
         const float* __restrict__ b0, const float* __restrict__ ba,
         const float* __restrict__ alpha_a, const float* __restrict__ gamma,
         const float* __restrict__ beta_ln, const float* __restrict__ bl,
         const float* __restrict__ bf, const float* __restrict__ alpha_f,
         const float* __restrict__ Wo, const float* __restrict__ bo,
         float* __restrict__ out) {
    extern __shared__ char smraw[];
    uint32_t* smA   = (uint32_t*)(smraw + OFF_A_B);
    uint32_t* smX   = (uint32_t*)(smraw + OFF_X_B);
    float*    red   = (float*)(smraw + OFF_RED_B);
    float*    stats = (float*)(smraw + OFF_ST_B);
    const uint32_t sA_u32 = s2u(smA);

    const int tid = threadIdx.x;
    const int warp = tid >> 5;
    const int lane = tid & 31;
    const int qr = lane >> 2, qc = lane & 3;
    const int row0 = blockIdx.x * TM;
    const uint32_t aBase = sA_u32 + (uint32_t)((lane & 15) * SAW * 4 + (lane >> 4) * 16);
    const int wlofs = (4 * warp) * 32 + lane;   // uint2 offset of this lane's frags

    for (int s = 0; s < TT; s++) {
        const int lo = max(row0, nn_off[s]);
        const int hi = min(row0 + TM, nn_off[s + 1]);
        if (lo >= hi) continue;
        __syncthreads();   // prior species fully done with smA/smX

        const uint2* wp0 = (const uint2*)(nn_wfragh + (size_t)(0 * 4 + s) * 32768) + wlofs;
        const uint2* wp1 = (const uint2*)(nn_wfragh + (size_t)(1 * 4 + s) * 32768) + wlofs;
        const uint2* wp2 = (const uint2*)(nn_wfragh + (size_t)(2 * 4 + s) * 32768) + wlofs;
        const uint2* wp3 = (const uint2*)(nn_wfragh + (size_t)(3 * 4 + s) * 32768) + wlofs;
        const float* b0s = b0 + s * D;
        const float* bas = ba + s * D;
        const float* aas = alpha_a + s * D;
        const float* gs  = gamma + s * D;
        const float* bts = beta_ln + s * D;
        const float* bls = bl + s * D;
        const float* bfs = bf + s * D;
        const float* afs = alpha_f + s * D;
        const float* wos = Wo + s * D;

        // gather density rows (fp16 into A)
#pragma unroll
        for (int it = 0; it < 8; it++) {
            int q = it * 256 + tid;
            int r = q >> 6, j = q & 63;
            uint2 t = make_uint2(0u, 0u);
            int gr = row0 + r;
            if (gr >= lo && gr < hi) {
                float4 v = __ldg((const float4*)(density + (size_t)nn_perm[gr] * D + j * 4));
                t = make_uint2(h2u(v.x, v.y), h2u(v.z, v.w));
            }
            *(uint2*)(smA + r * SAW + j * 2) = t;
        }
        __syncthreads();   // A ready for gemm

        float acc[2][4][4];

        // ===== layer 0: x = A @ W0^T + b0 (fp16(x) -> A and smX) =====
        ZACC(acc);
        gemm32(aBase, wp0, acc);
        __syncthreads();   // all warps done reading A
#pragma unroll
        for (int mt = 0; mt < 2; mt++)
#pragma unroll
            for (int nt = 0; nt < 4; nt++) {
                const int c0 = warp * 32 + nt * 8 + 2 * qc;
                float2 b2 = __ldg((const float2*)(b0s + c0));
                float z0 = acc[mt][nt][0] + b2.x, z1 = acc[mt][nt][1] + b2.y;
                float z2 = acc[mt][nt][2] + b2.x, z3 = acc[mt][nt][3] + b2.y;
                const int rr = mt * 16 + qr, cw = warp * 16 + nt * 4 + qc;
                uint32_t u0 = h2u(z0, z1), u1 = h2u(z2, z3);
                smA[rr * SAW + cw]       = u0;
                smA[(rr + 8) * SAW + cw] = u1;
                smX[rr * 128 + cw]       = u0;
                smX[(rr + 8) * 128 + cw] = u1;
            }
        __syncthreads();   // A ready

        // ===== hidden: h = LN(alpha_a * silu(x @ Wa^T + ba)) -> A =====
        ZACC(acc);
        gemm32(aBase, wp1, acc);
        __syncthreads();
        {
            float rs[4], rq[4];
#pragma unroll
            for (int i = 0; i < 4; i++) { rs[i] = 0.f; rq[i] = 0.f; }
#pragma unroll
            for (int mt = 0; mt < 2; mt++)
#pragma unroll
                for (int nt = 0; nt < 4; nt++) {
                    const int c0 = warp * 32 + nt * 8 + 2 * qc;
                    float2 b2 = __ldg((const float2*)(bas + c0));
                    float2 a2 = __ldg((const float2*)(aas + c0));
                    float h0 = a2.x * silu_s(acc[mt][nt][0] + b2.x);
                    float h1 = a2.y * silu_s(acc[mt][nt][1] + b2.y);
                    float h2 = a2.x * silu_s(acc[mt][nt][2] + b2.x);
                    float h3 = a2.y * silu_s(acc[mt][nt][3] + b2.y);
                    acc[mt][nt][0] = h0; acc[mt][nt][1] = h1;
                    acc[mt][nt][2] = h2; acc[mt][nt][3] = h3;
                    rs[mt * 2] += h0 + h1;       rq[mt * 2] += h0 * h0 + h1 * h1;
                    rs[mt * 2 + 1] += h2 + h3;   rq[mt * 2 + 1] += h2 * h2 + h3 * h3;
                }
#pragma unroll
            for (int i = 0; i < 4; i++) {
                rs[i] += __shfl_xor_sync(0xffffffffu, rs[i], 1);
                rs[i] += __shfl_xor_sync(0xffffffffu, rs[i], 2);
                rq[i] += __shfl_xor_sync(0xffffffffu, rq[i], 1);
                rq[i] += __shfl_xor_sync(0xffffffffu, rq[i], 2);
            }
            if (qc == 0) {
#pragma unroll
                for (int mt = 0; mt < 2; mt++) {
                    int r0 = mt * 16 + qr;
                    red[r0 * 8 + warp] = rs[mt * 2];
                    red[256 + r0 * 8 + warp] = rq[mt * 2];
                    red[(r0 + 8) * 8 + warp] = rs[mt * 2 + 1];
                    red[256 + (r0 + 8) * 8 + warp] = rq[mt * 2 + 1];
                }
            }
            __syncthreads();
            if (tid < 32) {
                float su = 0.f, sq = 0.f;
#pragma unroll
                for (int w = 0; w < 8; w++) { su += red[tid * 8 + w]; sq += red[256 + tid * 8 + w]; }
                float mu = su * (1.0f / D);
                stats[2 * tid] = mu;
                stats[2 * tid + 1] = rsqrtf(sq * (1.0f / D) - mu * mu + 1e-5f);
            }
            __syncthreads();
#pragma unroll
            for (int mt = 0; mt < 2; mt++) {
                const int rr = mt * 16 + qr;
                float2 st0 = *(const float2*)(stats + 2 * rr);
                float2 st1 = *(const float2*)(stats + 2 * (rr + 8));
#pragma unroll
                for (int nt = 0; nt < 4; nt++) {
                    const int c0 = warp * 32 + nt * 8 + 2 * qc;
                    float2 g2 = __ldg((const float2*)(gs + c0));
                    float2 bt2 = __ldg((const float2*)(bts + c0));
                    float n0 = g2.x * (acc[mt][nt][0] - st0.x) * st0.y + bt2.x;
                    float n1 = g2.y * (acc[mt][nt][1] - st0.x) * st0.y + bt2.y;
                    float n2 = g2.x * (acc[mt][nt][2] - st1.x) * st1.y + bt2.x;
                    float n3 = g2.y * (acc[mt][nt][3] - st1.x) * st1.y + bt2.y;
                    const int cw = warp * 16 + nt * 4 + qc;
                    smA[rr * SAW + cw]       = h2u(n0, n1);
                    smA[(rr + 8) * SAW + cw] = h2u(n2, n3);
                }
            }
        }
        __syncthreads();   // A ready

        // ===== residual: y = x + h @ Wl^T + bl =====
        ZACC(acc);
        gemm32(aBase, wp2, acc);
        __syncthreads();
#pragma unroll
        for (int mt = 0; mt < 2; mt++)
#pragma unroll
            for (int nt = 0; nt < 4; nt++) {
                const int c0 = warp * 32 + nt * 8 + 2 * qc;
                float2 b2 = __ldg((const float2*)(bls + c0));
                const int rr = mt * 16 + qr, cw = warp * 16 + nt * 4 + qc;
                float2 x0 = u2f(smX[rr * 128 + cw]);
                float2 x1 = u2f(smX[(rr + 8) * 128 + cw]);
                float y0 = x0.x + acc[mt][nt][0] + b2.x;
                float y1 = x0.y + acc[mt][nt][1] + b2.y;
                float y2 = x1.x + acc[mt][nt][2] + b2.x;
                float y3 = x1.y + acc[mt][nt][3] + b2.y;
                smA[rr * SAW + cw]       = h2u(y0, y1);
                smA[(rr + 8) * SAW + cw] = h2u(y2, y3);
            }
        __syncthreads();   // A ready

        // ===== tail: f = alpha_f * silu(y @ Wf^T + bf); out = f . Wo + bo =====
        ZACC(acc);
        gemm32(aBase, wp3, acc);
        {
            float rs[4];
#pragma unroll
            for (int i = 0; i < 4; i++) rs[i] = 0.f;
#pragma unroll
            for (int mt = 0; mt < 2; mt++)
#pragma unroll
                for (int nt = 0; nt < 4; nt++) {
                    const int c0 = warp * 32 + nt * 8 + 2 * qc;
                    float2 b2 = __ldg((const float2*)(bfs + c0));
                    float2 a2 = __ldg((const float2*)(afs + c0));
                    float2 w2 = __ldg((const float2*)(wos + c0));
                    rs[mt * 2]     += a2.x * silu_s(acc[mt][nt][0] + b2.x) * w2.x
                                    + a2.y * silu_s(acc[mt][nt][1] + b2.y) * w2.y;
                    rs[mt * 2 + 1] += a2.x * silu_s(acc[mt][nt][2] + b2.x) * w2.x
                                    + a2.y * silu_s(acc[mt][nt][3] + b2.y) * w2.y;
                }
#pragma unroll
            for (int i = 0; i < 4; i++) {
                rs[i] += __shfl_xor_sync(0xffffffffu, rs[i], 1);
                rs[i] += __shfl_xor_sync(0xffffffffu, rs[i], 2);
            }
            __syncthreads();   // red free from LN use
            if (qc == 0) {
#pragma unroll
                for (int mt = 0; mt < 2; mt++) {
                    int r0 = mt * 16 + qr;
                    red[r0 * 8 + warp] = rs[mt * 2];
                    red[(r0 + 8) * 8 + warp] = rs[mt * 2 + 1];
                }
            }
            __syncthreads();
            if (tid < 32) {
                int gr = row0 + tid;
                if (gr >= lo && gr < hi) {
                    float t = 0.f;
#pragma unroll
                    for (int w = 0; w < 8; w++) t += red[tid * 8 + w];
                    out[nn_perm[gr]] = t + __ldg(bo + s);
                }
            }
        }
    }
}

// ---------------- launch ----------------
extern "C" void kernel_launch(void* const* d_in, const int* in_sizes, int n_in,
                              void* d_out, int out_size) {
    const float* density = (const float*)d_in[0];
    const int*   species = (const int*)d_in[1];
    const float* W0      = (const float*)d_in[2];
    const float* b0      = (const float*)d_in[3];
    const float* Wa      = (const float*)d_in[4];
    const float* ba      = (const float*)d_in[5];
    const float* alpha_a = (const float*)d_in[6];
    const float* gamma   = (const float*)d_in[7];
    const float* beta_ln = (const float*)d_in[8];
    const float* Wl      = (const float*)d_in[9];
    const float* bl      = (const float*)d_in[10];
    const float* Wf      = (const float*)d_in[11];
    const float* bf      = (const float*)d_in[12];
    const float* alpha_f = (const float*)d_in[13];
    const float* Wo      = (const float*)d_in[14];
    const float* bo      = (const float*)d_in[15];
    float* out = (float*)d_out;

    cudaFuncSetAttribute(nn_fused, cudaFuncAttributeMaxDynamicSharedMemorySize, SMEM_BYTES);

    nn_combo<<<1, 1024>>>(species);
    nn_scatter<<<NA / 256, 256>>>(species);
    nn_prep<<<1024, 256>>>(W0, Wa, Wl, Wf);
    nn_fused<<<NTILES, NTH, SMEM_BYTES>>>(density, b0, ba, alpha_a, gamma, beta_ln,
                                          bl, bf, alpha_f, Wo, bo, out);
}

// round 17
// speedup vs baseline: 1.1088x; 1.0029x over previous
#include <cuda_runtime.h>
#include <cuda_fp16.h>
#include <cstdint>

#define NA 65536
#define D  256
#define TT 4
#define TM 32
#define NTILES (NA / TM)   // 2048
#define NTH 256
#define SAW 132            // A row stride in u32 (264 halves)

// ---- shared memory byte offsets ----
#define OFF_A_B   0                      // A tile fp16: 32 x 132 u32 = 16896 B
#define OFF_X_B   16896                  // x residual fp16: 32 x 128 u32 = 16384 B
#define OFF_RED_B 33280                  // 512 floats = 2048 B
#define OFF_ST_B  35328                  // 64 floats mu/inv = 256 B
#define SMEM_BYTES 35584

// ---------------- device scratch ----------------
__device__ int nn_off[TT + 1];
__device__ int nn_cur[TT];
__device__ int nn_perm[NA];
// fp16 frag weights: [mat(4)][species(4)][chunk(16)][g(32)][lane(32)][2xu32] = 2MB
__device__ __align__(16) uint32_t nn_wfragh[4 * TT * 16 * 2048];

// ---------------- combined init+hist+prefix ----------------
__global__ void nn_combo(const int* __restrict__ sp) {
    __shared__ int c[TT];
    int tid = threadIdx.x;
    if (tid < TT) { c[tid] = 0; nn_cur[tid] = 0; }
    __syncthreads();
    int l0 = 0, l1 = 0, l2 = 0, l3 = 0;
    for (int i = tid; i < NA / 4; i += 1024) {
        int4 v = __ldg((const int4*)sp + i);
        l0 += (v.x == 0) + (v.y == 0) + (v.z == 0) + (v.w == 0);
        l1 += (v.x == 1) + (v.y == 1) + (v.z == 1) + (v.w == 1);
        l2 += (v.x == 2) + (v.y == 2) + (v.z == 2) + (v.w == 2);
        l3 += (v.x == 3) + (v.y == 3) + (v.z == 3) + (v.w == 3);
    }
    if (l0) atomicAdd(&c[0], l0);
    if (l1) atomicAdd(&c[1], l1);
    if (l2) atomicAdd(&c[2], l2);
    if (l3) atomicAdd(&c[3], l3);
    __syncthreads();
    if (tid == 0) {
        int a = 0;
        for (int s = 0; s < TT; s++) { nn_off[s] = a; a += c[s]; }
        nn_off[TT] = a;
    }
}

__global__ void nn_scatter(const int* __restrict__ sp) {
    __shared__ int lc[TT];
    __shared__ int lb[TT];
    int tid = threadIdx.x;
    if (tid < TT) lc[tid] = 0;
    __syncthreads();
    int i = blockIdx.x * blockDim.x + tid;
    int s = 0, pos = 0;
    if (i < NA) { s = sp[i]; pos = atomicAdd(&lc[s], 1); }
    __syncthreads();
    if (tid < TT) {
        int n = lc[tid];
        lb[tid] = (n > 0) ? atomicAdd(&nn_cur[tid], n) : 0;
    }
    __syncthreads();
    if (i < NA) nn_perm[nn_off[s] + lb[s] + pos] = i;
}

// ---------------- helpers ----------------
__device__ __forceinline__ uint32_t h2u(float a, float b) {
    __half2 h = __floats2half2_rn(a, b);
    return *(uint32_t*)&h;
}
__device__ __forceinline__ float2 u2f(uint32_t u) {
    __half2 h = *(__half2*)&u;
    return __half22float2(h);
}
__device__ __forceinline__ uint32_t s2u(const void* p) {
    uint32_t a;
    asm("{ .reg .u64 t; cvta.to.shared.u64 t, %1; cvt.u32.u64 %0, t; }" : "=r"(a) : "l"(p));
    return a;
}

__device__ __forceinline__ void mma16(float* d, const uint32_t* a, const uint32_t* b) {
    asm volatile("mma.sync.aligned.m16n8k16.row.col.f32.f16.f16.f32 "
                 "{%0,%1,%2,%3}, {%4,%5,%6,%7}, {%8,%9}, {%0,%1,%2,%3};"
                 : "+f"(d[0]), "+f"(d[1]), "+f"(d[2]), "+f"(d[3])
                 : "r"(a[0]), "r"(a[1]), "r"(a[2]), "r"(a[3]), "r"(b[0]), "r"(b[1]));
}
__device__ __forceinline__ void ldm4(uint32_t* a, uint32_t addr) {
    asm volatile("ldmatrix.sync.aligned.m8n8.x4.shared.b16 {%0,%1,%2,%3}, [%4];"
                 : "=r"(a[0]), "=r"(a[1]), "=r"(a[2]), "=r"(a[3]) : "r"(addr));
}
__device__ __forceinline__ float silu_s(float z) {
    return z * (1.f / (1.f + __expf(-z)));
}

// ---------------- weight prepass: fp16 fragment packing ----------------
__global__ void nn_prep(const float* __restrict__ W0, const float* __restrict__ Wa,
                        const float* __restrict__ Wl, const float* __restrict__ Wf) {
    int p = blockIdx.x * 256 + threadIdx.x;
    int l = p & 31;
    int g = (p >> 5) & 31;
    int c = (p >> 10) & 15;
    int s = (p >> 14) & 3;
    int m = p >> 16;
    const float* W = (m == 0 ? W0 : m == 1 ? Wa : m == 2 ? Wl : Wf) + s * D * D;
    int n  = g * 8 + (l >> 2);
    int k0 = c * 16 + (l & 3) * 2;
    const float* wr = W + n * D;
    nn_wfragh[2 * p]     = h2u(__ldg(wr + k0),     __ldg(wr + k0 + 1));
    nn_wfragh[2 * p + 1] = h2u(__ldg(wr + k0 + 8), __ldg(wr + k0 + 9));
}

// ---------------- 32x256x256 GEMM: B global->regs double-buffered, A ldmatrix ----------------
// wp: this lane's B fragment pointer at chunk 0, group 4*warp (uint2 units).
__device__ __forceinline__ void gemm32(uint32_t aBase, const uint2* __restrict__ wp,
                                       float acc[2][4][4]) {
    uint2 bv[2][4];
#pragma unroll
    for (int nt = 0; nt < 4; nt++) bv[0][nt] = __ldg(wp + nt * 32);
#pragma unroll
    for (int nt = 0; nt < 4; nt++) bv[1][nt] = __ldg(wp + 1024 + nt * 32);
#pragma unroll
    for (int c = 0; c < 16; c++) {
        const int cur = c & 1;
        uint32_t a[2][4];
#pragma unroll
        for (int mt = 0; mt < 2; mt++)
            ldm4(a[mt], aBase + (uint32_t)(mt * 16 * SAW * 4 + c * 32));
#pragma unroll
        for (int mt = 0; mt < 2; mt++)
#pragma unroll
            for (int nt = 0; nt < 4; nt++)
                mma16(acc[mt][nt], a[mt], (const uint32_t*)&bv[cur][nt]);
        if (c + 2 < 16) {
#pragma unroll
            for (int nt = 0; nt < 4; nt++)
                bv[cur][nt] = __ldg(wp + (c + 2) * 1024 + nt * 32);
        }
    }
}

#define ZACC(acc) \
    _Pragma("unroll") for (int mt = 0; mt < 2; mt++) \
    _Pragma("unroll") for (int nt = 0; nt < 4; nt++) \
    _Pragma("unroll") for (int q = 0; q < 4; q++) (acc)[mt][nt][q] = 0.f;

// ---------------- fused expert MLP ----------------
__global__ void __launch_bounds__(NTH, 4)
nn_fused(const float* __restrict__ density,
         const float* __restrict__ b0, const float* __restrict__ ba,
         const float* __restrict__ alpha_a, const float* __restrict__ gamma,
         const float* __restrict__ beta_ln, const float* __restrict__ bl,
         const float* __restrict__ bf, const float* __restrict__ alpha_f,
         const float* __restrict__ Wo, const float* __restrict__ bo,
         float* __restrict__ out) {
    extern __shared__ char smraw[];
    uint32_t* smA   = (uint32_t*)(smraw + OFF_A_B);
    uint32_t* smX   = (uint32_t*)(smraw + OFF_X_B);
    float*    red   = (float*)(smraw + OFF_RED_B);
    float*    stats = (float*)(smraw + OFF_ST_B);
    const uint32_t sA_u32 = s2u(smA);

    const int tid = threadIdx.x;
    const int warp = tid >> 5;
    const int lane = tid & 31;
    const int qr = lane >> 2, qc = lane & 3;
    const int row0 = blockIdx.x * TM;
    const uint32_t aBase = sA_u32 + (uint32_t)((lane & 15) * SAW * 4 + (lane >> 4) * 16);
    const int wlofs = (4 * warp) * 32 + lane;   // uint2 offset of this lane's frags

    for (int s = 0; s < TT; s++) {
        const int lo = max(row0, nn_off[s]);
        const int hi = min(row0 + TM, nn_off[s + 1]);
        if (lo >= hi) continue;
        __syncthreads();   // prior species fully done with smA/smX

        const uint2* wp0 = (const uint2*)(nn_wfragh + (size_t)(0 * 4 + s) * 32768) + wlofs;
        const uint2* wp1 = (const uint2*)(nn_wfragh + (size_t)(1 * 4 + s) * 32768) + wlofs;
        const uint2* wp2 = (const uint2*)(nn_wfragh + (size_t)(2 * 4 + s) * 32768) + wlofs;
        const uint2* wp3 = (const uint2*)(nn_wfragh + (size_t)(3 * 4 + s) * 32768) + wlofs;
        const float* b0s = b0 + s * D;
        const float* bas = ba + s * D;
        const float* aas = alpha_a + s * D;
        const float* gs  = gamma + s * D;
        const float* bts = beta_ln + s * D;
        const float* bls = bl + s * D;
        const float* bfs = bf + s * D;
        const float* afs = alpha_f + s * D;
        const float* wos = Wo + s * D;

        // gather density rows (fp16 into A)
#pragma unroll
        for (int it = 0; it < 8; it++) {
            int q = it * 256 + tid;
            int r = q >> 6, j = q & 63;
            uint2 t = make_uint2(0u, 0u);
            int gr = row0 + r;
            if (gr >= lo && gr < hi) {
                float4 v = __ldg((const float4*)(density + (size_t)nn_perm[gr] * D + j * 4));
                t = make_uint2(h2u(v.x, v.y), h2u(v.z, v.w));
            }
            *(uint2*)(smA + r * SAW + j * 2) = t;
        }
        __syncthreads();   // A ready for gemm

        float acc[2][4][4];

        // ===== layer 0: x = A @ W0^T + b0 (fp16(x) -> A and smX) =====
        ZACC(acc);
        gemm32(aBase, wp0, acc);
        __syncthreads();   // all warps done reading A
#pragma unroll
        for (int mt = 0; mt < 2; mt++)
#pragma unroll
            for (int nt = 0; nt < 4; nt++) {
                const int c0 = warp * 32 + nt * 8 + 2 * qc;
                float2 b2 = __ldg((const float2*)(b0s + c0));
                float z0 = acc[mt][nt][0] + b2.x, z1 = acc[mt][nt][1] + b2.y;
                float z2 = acc[mt][nt][2] + b2.x, z3 = acc[mt][nt][3] + b2.y;
                const int rr = mt * 16 + qr, cw = warp * 16 + nt * 4 + qc;
                uint32_t u0 = h2u(z0, z1), u1 = h2u(z2, z3);
                smA[rr * SAW + cw]       = u0;
                smA[(rr + 8) * SAW + cw] = u1;
                smX[rr * 128 + cw]       = u0;
                smX[(rr + 8) * 128 + cw] = u1;
            }
        __syncthreads();   // A ready

        // ===== hidden: h = LN(alpha_a * silu(x @ Wa^T + ba)) -> A =====
        ZACC(acc);
        gemm32(aBase, wp1, acc);
        __syncthreads();
        {
            float rs[4], rq[4];
#pragma unroll
            for (int i = 0; i < 4; i++) { rs[i] = 0.f; rq[i] = 0.f; }
#pragma unroll
            for (int mt = 0; mt < 2; mt++)
#pragma unroll
                for (int nt = 0; nt < 4; nt++) {
                    const int c0 = warp * 32 + nt * 8 + 2 * qc;
                    float2 b2 = __ldg((const float2*)(bas + c0));
                    float2 a2 = __ldg((const float2*)(aas + c0));
                    float h0 = a2.x * silu_s(acc[mt][nt][0] + b2.x);
                    float h1 = a2.y * silu_s(acc[mt][nt][1] + b2.y);
                    float h2 = a2.x * silu_s(acc[mt][nt][2] + b2.x);
                    float h3 = a2.y * silu_s(acc[mt][nt][3] + b2.y);
                    acc[mt][nt][0] = h0; acc[mt][nt][1] = h1;
                    acc[mt][nt][2] = h2; acc[mt][nt][3] = h3;
                    rs[mt * 2] += h0 + h1;       rq[mt * 2] += h0 * h0 + h1 * h1;
                    rs[mt * 2 + 1] += h2 + h3;   rq[mt * 2 + 1] += h2 * h2 + h3 * h3;
                }
#pragma unroll
            for (int i = 0; i < 4; i++) {
                rs[i] += __shfl_xor_sync(0xffffffffu, rs[i], 1);
                rs[i] += __shfl_xor_sync(0xffffffffu, rs[i], 2);
                rq[i] += __shfl_xor_sync(0xffffffffu, rq[i], 1);
                rq[i] += __shfl_xor_sync(0xffffffffu, rq[i], 2);
            }
            if (qc == 0) {
#pragma unroll
                for (int mt = 0; mt < 2; mt++) {
                    int r0 = mt * 16 + qr;
                    red[r0 * 8 + warp] = rs[mt * 2];
                    red[256 + r0 * 8 + warp] = rq[mt * 2];
                    red[(r0 + 8) * 8 + warp] = rs[mt * 2 + 1];
                    red[256 + (r0 + 8) * 8 + warp] = rq[mt * 2 + 1];
                }
            }
            __syncthreads();
            if (tid < 32) {
                float su = 0.f, sq = 0.f;
#pragma unroll
                for (int w = 0; w < 8; w++) { su += red[tid * 8 + w]; sq += red[256 + tid * 8 + w]; }
                float mu = su * (1.0f / D);
                stats[2 * tid] = mu;
                stats[2 * tid + 1] = rsqrtf(sq * (1.0f / D) - mu * mu + 1e-5f);
            }
            __syncthreads();
#pragma unroll
            for (int mt = 0; mt < 2; mt++) {
                const int rr = mt * 16 + qr;
                float2 st0 = *(const float2*)(stats + 2 * rr);
                float2 st1 = *(const float2*)(stats + 2 * (rr + 8));
#pragma unroll
                for (int nt = 0; nt < 4; nt++) {
                    const int c0 = warp * 32 + nt * 8 + 2 * qc;
                    float2 g2 = __ldg((const float2*)(gs + c0));
                    float2 bt2 = __ldg((const float2*)(bts + c0));
                    float n0 = g2.x * (acc[mt][nt][0] - st0.x) * st0.y + bt2.x;
                    float n1 = g2.y * (acc[mt][nt][1] - st0.x) * st0.y + bt2.y;
                    float n2 = g2.x * (acc[mt][nt][2] - st1.x) * st1.y + bt2.x;
                    float n3 = g2.y * (acc[mt][nt][3] - st1.x) * st1.y + bt2.y;
                    const int cw = warp * 16 + nt * 4 + qc;
                    smA[rr * SAW + cw]       = h2u(n0, n1);
                    smA[(rr + 8) * SAW + cw] = h2u(n2, n3);
                }
            }
        }
        __syncthreads();   // A ready

        // ===== residual: y = x + h @ Wl^T + bl =====
        ZACC(acc);
        gemm32(aBase, wp2, acc);
        __syncthreads();
#pragma unroll
        for (int mt = 0; mt < 2; mt++)
#pragma unroll
            for (int nt = 0; nt < 4; nt++) {
                const int c0 = warp * 32 + nt * 8 + 2 * qc;
                float2 b2 = __ldg((const float2*)(bls + c0));
                const int rr = mt * 16 + qr, cw = warp * 16 + nt * 4 + qc;
                float2 x0 = u2f(smX[rr * 128 + cw]);
                float2 x1 = u2f(smX[(rr + 8) * 128 + cw]);
                float y0 = x0.x + acc[mt][nt][0] + b2.x;
                float y1 = x0.y + acc[mt][nt][1] + b2.y;
                float y2 = x1.x + acc[mt][nt][2] + b2.x;
                float y3 = x1.y + acc[mt][nt][3] + b2.y;
                smA[rr * SAW + cw]       = h2u(y0, y1);
                smA[(rr + 8) * SAW + cw] = h2u(y2, y3);
            }
        __syncthreads();   // A ready

        // ===== tail: f = alpha_f * silu(y @ Wf^T + bf); out = f . Wo + bo =====
        ZACC(acc);
        gemm32(aBase, wp3, acc);
        {
            float rs[4];
#pragma unroll
            for (int i = 0; i < 4; i++) rs[i] = 0.f;
#pragma unroll
            for (int mt = 0; mt < 2; mt++)
#pragma unroll
                for (int nt = 0; nt < 4; nt++) {
                    const int c0 = warp * 32 + nt * 8 + 2 * qc;
                    float2 b2 = __ldg((const float2*)(bfs + c0));
                    float2 a2 = __ldg((const float2*)(afs + c0));
                    float2 w2 = __ldg((const float2*)(wos + c0));
                    rs[mt * 2]     += a2.x * silu_s(acc[mt][nt][0] + b2.x) * w2.x
                                    + a2.y * silu_s(acc[mt][nt][1] + b2.y) * w2.y;
                    rs[mt * 2 + 1] += a2.x * silu_s(acc[mt][nt][2] + b2.x) * w2.x
                                    + a2.y * silu_s(acc[mt][nt][3] + b2.y) * w2.y;
                }
#pragma unroll
            for (int i = 0; i < 4; i++) {
                rs[i] += __shfl_xor_sync(0xffffffffu, rs[i], 1);
                rs[i] += __shfl_xor_sync(0xffffffffu, rs[i], 2);
            }
            __syncthreads();   // red free from LN use
            if (qc == 0) {
#pragma unroll
                for (int mt = 0; mt < 2; mt++) {
                    int r0 = mt * 16 + qr;
                    red[r0 * 8 + warp] = rs[mt * 2];
                    red[(r0 + 8) * 8 + warp] = rs[mt * 2 + 1];
                }
            }
            __syncthreads();
            if (tid < 32) {
                int gr = row0 + tid;
                if (gr >= lo && gr < hi) {
                    float t = 0.f;
#pragma unroll
                    for (int w = 0; w < 8; w++) t += red[tid * 8 + w];
                    out[nn_perm[gr]] = t + __ldg(bo + s);
                }
            }
        }
    }
}

// ---------------- launch ----------------
extern "C" void kernel_launch(void* const* d_in, const int* in_sizes, int n_in,
                              void* d_out, int out_size) {
    const float* density = (const float*)d_in[0];
    const int*   species = (const int*)d_in[1];
    const float* W0      = (const float*)d_in[2];
    const float* b0      = (const float*)d_in[3];
    const float* Wa      = (const float*)d_in[4];
    const float* ba      = (const float*)d_in[5];
    const float* alpha_a = (const float*)d_in[6];
    const float* gamma   = (const float*)d_in[7];
    const float* beta_ln = (const float*)d_in[8];
    const float* Wl      = (const float*)d_in[9];
    const float* bl      = (const float*)d_in[10];
    const float* Wf      = (const float*)d_in[11];
    const float* bf      = (const float*)d_in[12];
    const float* alpha_f = (const float*)d_in[13];
    const float* Wo      = (const float*)d_in[14];
    const float* bo      = (const float*)d_in[15];
    float* out = (float*)d_out;

    cudaFuncSetAttribute(nn_fused, cudaFuncAttributeMaxDynamicSharedMemorySize, SMEM_BYTES);

    nn_combo<<<1, 1024>>>(species);
    nn_scatter<<<NA / 256, 256>>>(species);
    nn_prep<<<1024, 256>>>(W0, Wa, Wl, Wf);
    nn_fused<<<NTILES, NTH, SMEM_BYTES>>>(density, b0, ba, alpha_a, gamma, beta_ln,
                                          bl, bf, alpha_f, Wo, bo, out);
}